// round 8
// baseline (speedup 1.0000x reference)
#include <cuda_runtime.h>
#include <cuda_fp16.h>

// Problem constants (fixed-shape problem)
#define NB 20000      // nodes
#define BB 64         // batch
#define EE 1280000    // edges

// Persistent front kernel geometry: 444 blocks x 512 threads, 3 blocks/SM on 148 SMs
// => all blocks co-resident GUARANTEED by __launch_bounds__(512, 3)  (regs<=42, smem 8.5KB)
#define NBLK 444
#define NTHR 512
#define GSTRIDE (NBLK * NTHR)   // 227328 threads

// ---------------- scratch (device globals; no runtime allocation) ----------------
__device__ __half    g_xth[NB * BB];                  // x transposed [N,B] fp16 (2.56 MB)
__device__ __align__(16) int g_count[NB];             // histogram; ZERO at launch entry
__device__ __align__(16) int g_rank[EE];              // per-edge rank in dst bucket
__device__ __align__(16) int g_row_start[NB + 4];     // CSR offsets (padded for int4)
__device__ long long g_edge[EE];                      // packed (coef<<32 | src), sorted
// software grid barrier state (generation-numbered; monotonic across graph replays)
__device__ volatile unsigned g_arrive[NBLK];
__device__ volatile unsigned g_release;

__device__ __forceinline__ long long pack_edge(int s, float c) {
    return ((long long)__float_as_int(c) << 32) | (unsigned int)s;
}

// All-resident spin barrier. Each thread fences its stores, block syncs, then
// thread 0 arrives; block 0 observes all arrivals and publishes g_release=gen.
__device__ __forceinline__ void grid_bar(unsigned gen) {
    __threadfence();
    __syncthreads();
    if (blockIdx.x == 0) {
        const int t = threadIdx.x;
        if (t > 0 && t < NBLK) {
            while (g_arrive[t] < gen) __nanosleep(64);
        }
        __syncthreads();
        if (t == 0) g_release = gen;
    } else {
        if (threadIdx.x == 0) {
            g_arrive[blockIdx.x] = gen;
            while (g_release < gen) __nanosleep(64);
        }
    }
    __syncthreads();
    __threadfence();
}

// ---------------- K1: fused front (rank-hist + transpose | scan | scatter) --------
__global__ __launch_bounds__(NTHR, 3) void k_front(const float* __restrict__ x,
                                                   const int* __restrict__ src,
                                                   const int* __restrict__ dst,
                                                   const float* __restrict__ adj,
                                                   const float* __restrict__ w) {
    __shared__ float tile[2][32][33];
    __shared__ int   s_wsum[16];
    __shared__ unsigned s_gen;

    const int tid  = threadIdx.x;
    const int bid  = blockIdx.x;
    const int gtid = bid * NTHR + tid;

    if (tid == 0) s_gen = g_release;     // barrier generation base (stable at entry)
    __syncthreads();
    const unsigned gen0 = s_gen;

    // ---- Phase 1a: rank-histogram  rank[e] = atomicAdd(count[dst[e]], 1) ----
    for (int i = gtid; i < EE / 4; i += GSTRIDE) {
        int4 d4 = reinterpret_cast<const int4*>(dst)[i];
        int4 r4;
        r4.x = atomicAdd(&g_count[d4.x], 1);
        r4.y = atomicAdd(&g_count[d4.y], 1);
        r4.z = atomicAdd(&g_count[d4.z], 1);
        r4.w = atomicAdd(&g_count[d4.w], 1);
        reinterpret_cast<int4*>(g_rank)[i] = r4;
    }

    // ---- Phase 1b: transpose x [B,N] -> xth [N,B] fp16 (overlaps atomics) ----
    {
        const int st = tid >> 8;             // 0/1: which b-halftile
        const int t8 = tid & 255;
        const int tx = t8 & 31, ty = t8 >> 5;
        __half2* __restrict__ xth2 = reinterpret_cast<__half2*>(g_xth);
        for (int p = bid; p < 625; p += NBLK) {   // 625 n-tiles of 32
            const int n0 = p * 32, b0 = st * 32;
            #pragma unroll
            for (int i = 0; i < 32; i += 8)
                tile[st][ty + i][tx] = x[(b0 + ty + i) * NB + n0 + tx];
            __syncthreads();
            #pragma unroll
            for (int i = 0; i < 2; i++) {
                int idx = i * 256 + t8;
                int nl = idx >> 4;           // 0..31
                int bp = idx & 15;           // half2 pair
                xth2[(n0 + nl) * 32 + (b0 >> 1) + bp] =
                    __floats2half2_rn(tile[st][2 * bp][nl], tile[st][2 * bp + 1][nl]);
            }
            __syncthreads();
        }
    }

    grid_bar(gen0 + 1);

    // ---- Phase 2: exclusive scan of g_count (block 0 only; 500 threads x 40) ----
    if (bid == 0) {
        const int lane = tid & 31, wid = tid >> 5;
        int cnt[40];
        int sum = 0;
        if (tid < 500) {
            const int4* c4 = reinterpret_cast<const int4*>(g_count + tid * 40);
            #pragma unroll
            for (int k = 0; k < 10; k++) {
                int4 v = c4[k];
                cnt[4 * k] = v.x; cnt[4 * k + 1] = v.y;
                cnt[4 * k + 2] = v.z; cnt[4 * k + 3] = v.w;
                sum += v.x + v.y + v.z + v.w;
            }
        }
        // block-wide exclusive scan of per-thread sums (16 warps)
        int v = sum;
        #pragma unroll
        for (int o = 1; o < 32; o <<= 1) {
            int u = __shfl_up_sync(0xFFFFFFFFu, v, o);
            if (lane >= o) v += u;
        }
        if (lane == 31) s_wsum[wid] = v;
        __syncthreads();
        if (wid == 0 && lane < 16) {
            int wv = s_wsum[lane];
            #pragma unroll
            for (int o = 1; o < 16; o <<= 1) {
                int u = __shfl_up_sync(0xFFFFu, wv, o);
                if (lane >= o) wv += u;
            }
            s_wsum[lane] = wv;
        }
        __syncthreads();
        int excl = ((wid > 0) ? s_wsum[wid - 1] : 0) + (v - sum);
        if (tid < 500) {
            int4* rs4 = reinterpret_cast<int4*>(g_row_start + tid * 40);
            int run = excl;
            #pragma unroll
            for (int k = 0; k < 10; k++) {
                int4 o;
                o.x = run; run += cnt[4 * k];
                o.y = run; run += cnt[4 * k + 1];
                o.z = run; run += cnt[4 * k + 2];
                o.w = run; run += cnt[4 * k + 3];
                rs4[k] = o;
            }
            if (tid == 499) g_row_start[NB] = run;   // = EE
        }
    }

    grid_bar(gen0 + 2);

    // ---- Phase 3: atomic-free scatter + restore g_count zero invariant ----
    for (int i = gtid; i < NB; i += GSTRIDE) g_count[i] = 0;

    for (int t = gtid; t < EE / 8; t += GSTRIDE) {
        const int4*   src4 = reinterpret_cast<const int4*>(src);
        const int4*   dst4 = reinterpret_cast<const int4*>(dst);
        const float4* adj4 = reinterpret_cast<const float4*>(adj);
        const float4* w4p  = reinterpret_cast<const float4*>(w);
        const int4*   rnk4 = reinterpret_cast<const int4*>(g_rank);

        int4   sA = src4[2 * t],  sB = src4[2 * t + 1];
        int4   dA = dst4[2 * t],  dB = dst4[2 * t + 1];
        float4 aA = adj4[2 * t],  aB = adj4[2 * t + 1];
        float4 wA = w4p[2 * t],   wB = w4p[2 * t + 1];
        int4   rA = rnk4[2 * t],  rB = rnk4[2 * t + 1];

        int p0 = g_row_start[dA.x] + rA.x;
        int p1 = g_row_start[dA.y] + rA.y;
        int p2 = g_row_start[dA.z] + rA.z;
        int p3 = g_row_start[dA.w] + rA.w;
        int p4 = g_row_start[dB.x] + rB.x;
        int p5 = g_row_start[dB.y] + rB.y;
        int p6 = g_row_start[dB.z] + rB.z;
        int p7 = g_row_start[dB.w] + rB.w;

        g_edge[p0] = pack_edge(sA.x, aA.x * wA.x);
        g_edge[p1] = pack_edge(sA.y, aA.y * wA.y);
        g_edge[p2] = pack_edge(sA.z, aA.z * wA.z);
        g_edge[p3] = pack_edge(sA.w, aA.w * wA.w);
        g_edge[p4] = pack_edge(sB.x, aB.x * wB.x);
        g_edge[p5] = pack_edge(sB.y, aB.y * wB.y);
        g_edge[p6] = pack_edge(sB.z, aB.z * wB.z);
        g_edge[p7] = pack_edge(sB.w, aB.w * wB.w);
    }
    // kernel boundary = global sync before spmm
}

// ---------------- K2: gather-SpMM + fused epilogue (unchanged from R7) ------------
__global__ __launch_bounds__(512) void k_spmm(const float* __restrict__ x,      // for x[0, :]
                                              const float* __restrict__ self_w,
                                              const float* __restrict__ bias,
                                              float* __restrict__ out) {
    __shared__ long long s_pay[16][33];   // 32 payloads per warp (+pad)
    __shared__ float2    s_red[8][32];    // partial from odd warp
    __shared__ float     s_out[8][65];    // [node][batch] staged output

    const int warp = threadIdx.x >> 5;
    const int lane = threadIdx.x & 31;
    const int node = warp >> 1;           // 0..7
    const int half = warp & 1;
    const int n = blockIdx.x * 8 + node;  // NB = 2500 * 8 exact

    const int start = g_row_start[n];
    const int end   = g_row_start[n + 1];
    const int mid   = (start + end) >> 1;
    const int lo    = half ? mid : start;
    const int hi    = half ? end : mid;

    const __half2* __restrict__ xth2 = reinterpret_cast<const __half2*>(g_xth);

    float ax = 0.f, ay = 0.f;

    for (int base = lo; base < hi; base += 32) {
        const int cnt = min(32, hi - base);
        if (lane < cnt) s_pay[warp][lane] = g_edge[base + lane];
        __syncwarp();

        int k = 0;
        for (; k + 8 <= cnt; k += 8) {
            long long p[8];
            #pragma unroll
            for (int u = 0; u < 8; u++) p[u] = s_pay[warp][k + u];
            #pragma unroll
            for (int u = 0; u < 8; u++) {
                unsigned int s = (unsigned int)p[u];
                float c = __int_as_float((int)(p[u] >> 32));
                float2 v = __half22float2(xth2[s * 32 + lane]);
                ax = fmaf(c, v.x, ax);
                ay = fmaf(c, v.y, ay);
            }
        }
        for (; k < cnt; k++) {
            long long p = s_pay[warp][k];
            unsigned int s = (unsigned int)p;
            float c = __int_as_float((int)(p >> 32));
            float2 v = __half22float2(xth2[s * 32 + lane]);
            ax = fmaf(c, v.x, ax);
            ay = fmaf(c, v.y, ay);
        }
        __syncwarp();
    }

    if (half == 1) s_red[node][lane] = make_float2(ax, ay);
    __syncthreads();

    if (half == 0) {
        float2 r = s_red[node][lane];
        ax += r.x;  ay += r.y;
        const float sl = x[n] * self_w[n];   // x[0*N + n]  (fp32, exact)
        const float bv = bias[n];
        s_out[node][2 * lane]     = fmaxf(ax * sl + bv, 0.0f);
        s_out[node][2 * lane + 1] = fmaxf(ay * sl + bv, 0.0f);
    }
    __syncthreads();

    // coalesced output: 512 threads = 8 nodes x 64 batch
    const int j = threadIdx.x & 7;        // node within block
    const int b = threadIdx.x >> 3;       // batch
    out[b * NB + blockIdx.x * 8 + j] = s_out[j][b];
}

// ---------------- launch -----------------------------------------------------------
extern "C" void kernel_launch(void* const* d_in, const int* in_sizes, int n_in,
                              void* d_out, int out_size) {
    const float* x      = (const float*)d_in[0];   // [B, N]
    const float* adj    = (const float*)d_in[1];   // [E]
    const float* w      = (const float*)d_in[2];   // [E]
    const float* self_w = (const float*)d_in[3];   // [N]
    const float* bias   = (const float*)d_in[4];   // [N]
    const int*   src    = (const int*)d_in[5];     // [E]
    const int*   dst    = (const int*)d_in[6];     // [E]
    float*       out    = (float*)d_out;           // [B, N]

    k_front<<<NBLK, NTHR>>>(x, src, dst, adj, w);  // hist+transpose | scan | scatter

    k_spmm<<<NB / 8, 512>>>(x, self_w, bias, out);
}